// round 11
// baseline (speedup 1.0000x reference)
#include <cuda_runtime.h>
#include <math.h>
#include <stdint.h>

// Problem constants
#define BB    64
#define TT    128
#define INW   128
#define HHD   512
#define NND   2048
#define WWD   64
#define OUTW  128
#define RRD   4
#define CTRL  384            // IN + R*W
#define KGATE 896            // CTRL + H  (14 tiles of 64)
#define JGATE 2048           // 4*H
#define JOK   448            // OUT + (R+1)*W
#define EPSF  1e-8f
#define NCHUNK 32            // sim/stats chunks per (b,r)

// ------------------------- persistent device state -------------------------
__device__ float g_h[2][BB * HHD];             // ping-pong hidden state
__device__ float g_c[BB * HHD];
__device__ float g_M[BB * NND * WWD];          // 33.5 MB
__device__ float g_usage[BB * NND];
__device__ float g_rw[2][BB * RRD * NND];      // ping-pong read weights
__device__ float g_read_vec[BB * RRD * WWD];
__device__ float g_sim[BB * RRD * NND];        // raw cosine sims
__device__ float2 g_stats[BB * RRD * NCHUNK];  // per-chunk (max, sumexp)
__device__ float g_Kn[BB * RRD * WWD];         // normalized read keys
__device__ float g_wkey[BB * WWD];             // write key
__device__ int   g_lu[BB];                     // argmin(usage) per batch

// ------------------------------- reset -------------------------------------
__global__ void k_reset() {
    long idx = (long)blockIdx.x * blockDim.x + threadIdx.x;
    if (idx < (long)BB * NND * WWD) g_M[idx] = 1e-6f;
    if (idx < BB * HHD) { g_h[0][idx] = 0.f; g_h[1][idx] = 0.f; g_c[idx] = 0.f; }
    if (idx < BB * NND) g_usage[idx] = 0.f;
    if (idx < BB * RRD * NND) { g_rw[0][idx] = 0.f; g_rw[1][idx] = 0.f; }
    if (idx < BB * RRD * WWD) g_read_vec[idx] = 0.f;
    if (idx < BB) g_lu[idx] = 0;
}

__device__ __forceinline__ float sigm(float x) { return 1.f / (1.f + expf(-x)); }

// packed f32x2 FMA: d = a * b + d  (componentwise, RN — bit-identical to FFMA)
__device__ __forceinline__ void fma2(unsigned long long& d,
                                     unsigned long long a, unsigned long long b) {
    asm("fma.rn.f32x2 %0, %1, %2, %0;" : "+l"(d) : "l"(a), "l"(b));
}

// ==================== K1: gates GEMM (f32x2) + LSTM epilogue ================
// grid 128 blocks x 256 threads, 1 block/SM. Block owns hh0 = bid*4: the 4
// hidden units across all 4 gates (16 j), all 64 batches, full K=896.
// x tile stored DUPLICATED (x,x) float2 pairs; W transposed to j-pair float2.
// Inner loop per 2k: 3 LDS.128 + 4 fma.f32x2 -> FMA-pipe inst count halved.
#define XP 132   // xs2d float pitch (66 float2, 16B-aligned rows)
#define WP 132   // wst2 float pitch per j-pair row
__global__ void __launch_bounds__(256) k_gates(
    const float* __restrict__ xt,
    const float* __restrict__ Wih, const float* __restrict__ Whh,
    const float* __restrict__ bih, const float* __restrict__ bhh,
    int sel)
{
    __shared__ __align__(16) float xs2d[BB * XP];   // 33.8 KB, [b][k dup pairs]
    __shared__ __align__(16) float wst2[8 * WP];    // 4.2 KB,  [jp][k pairs]
    __shared__ float sacc[16][65];                  // 4.2 KB,  [jidx][b]

    const int tid = threadIdx.x;
    const int hp  = tid & 7;        // j-pair index 0..7
    const int bq  = tid >> 3;       // 0..31 -> batches 2bq, 2bq+1
    const int hh0 = blockIdx.x * 4;
    const float* __restrict__ hr = g_h[sel];

    // staging indices (also used for W rows)
    const int xb   = tid >> 4;      // 0..15
    const int xk4  = tid & 15;      // k-group
    const int jidx = tid >> 4;      // W row 0..15
    const int jr   = hh0 + (jidx & 3) + (jidx >> 2) * 512;

    unsigned long long acc_b0 = 0ULL, acc_b1 = 0ULL;  // (j0,j1) sums for b0,b1

    float4 xreg[4];
    float4 wreg;

    // prologue: load tile 0 into registers
    {
        const int k0 = 0;
#pragma unroll
        for (int li = 0; li < 4; ++li) {
            int b = xb + 16 * li;
            int k = k0 + xk4 * 4;
            const float* src;
            if (k < INW)       src = xt + b * INW + k;
            else if (k < CTRL) src = g_read_vec + b * (RRD * WWD) + (k - INW);
            else               src = hr + b * HHD + (k - CTRL);
            xreg[li] = *reinterpret_cast<const float4*>(src);
        }
        int k = k0 + xk4 * 4;
        const float* src = (k < CTRL) ? (Wih + (size_t)jr * CTRL + k)
                                      : (Whh + (size_t)jr * HHD + (k - CTRL));
        wreg = *reinterpret_cast<const float4*>(src);
    }

    const ulonglong2* xap = (const ulonglong2*)(xs2d + (2 * bq) * XP);
    const ulonglong2* xbp = (const ulonglong2*)(xs2d + (2 * bq + 1) * XP);
    const ulonglong2* wp  = (const ulonglong2*)(wst2 + hp * WP);

    for (int tl = 0; tl < 14; ++tl) {
        // commit staged registers to smem (x duplicated, W transposed)
#pragma unroll
        for (int li = 0; li < 4; ++li) {
            int b = xb + 16 * li;
            float4 v = xreg[li];
            float4* dst = (float4*)(xs2d + b * XP + xk4 * 8);
            dst[0] = make_float4(v.x, v.x, v.y, v.y);
            dst[1] = make_float4(v.z, v.z, v.w, v.w);
        }
        {
            float4 v = wreg;
            int jp = jidx >> 1, par = jidx & 1;
            float* wd = wst2 + jp * WP + xk4 * 8 + par;
            wd[0] = v.x; wd[2] = v.y; wd[4] = v.z; wd[6] = v.w;
        }
        __syncthreads();

        // prefetch next tile
        if (tl + 1 < 14) {
            const int k0 = (tl + 1) * 64;
#pragma unroll
            for (int li = 0; li < 4; ++li) {
                int b = xb + 16 * li;
                int k = k0 + xk4 * 4;
                const float* src;
                if (k < INW)       src = xt + b * INW + k;
                else if (k < CTRL) src = g_read_vec + b * (RRD * WWD) + (k - INW);
                else               src = hr + b * HHD + (k - CTRL);
                xreg[li] = *reinterpret_cast<const float4*>(src);
            }
            int k = k0 + xk4 * 4;
            const float* src = (k < CTRL) ? (Wih + (size_t)jr * CTRL + k)
                                          : (Whh + (size_t)jr * HHD + (k - CTRL));
            wreg = *reinterpret_cast<const float4*>(src);
        }

        // compute current tile: 32 k2-steps (2 k each)
#pragma unroll
        for (int k2 = 0; k2 < 32; ++k2) {
            ulonglong2 w  = wp[k2];     // (wj0,wj1)[k], (wj0,wj1)[k+1]
            ulonglong2 x0 = xap[k2];    // (x,x)[k], (x,x)[k+1] for b0
            ulonglong2 x1 = xbp[k2];
            fma2(acc_b0, x0.x, w.x); fma2(acc_b0, x0.y, w.y);
            fma2(acc_b1, x1.x, w.x); fma2(acc_b1, x1.y, w.y);
        }
        __syncthreads();
    }

    // unpack and stage accumulators: sacc[jidx][b]
    {
        float l0, h0, l1, h1;
        asm("mov.b64 {%0, %1}, %2;" : "=f"(l0), "=f"(h0) : "l"(acc_b0));
        asm("mov.b64 {%0, %1}, %2;" : "=f"(l1), "=f"(h1) : "l"(acc_b1));
        sacc[2 * hp][2 * bq]     = l0;
        sacc[2 * hp + 1][2 * bq] = h0;
        sacc[2 * hp][2 * bq + 1]     = l1;
        sacc[2 * hp + 1][2 * bq + 1] = h1;
    }
    __syncthreads();

    // LSTM pointwise: thread t -> b = t&63, dd = t>>6 (0..3), hh = hh0+dd
    {
        const int b  = tid & 63;
        const int dd = tid >> 6;
        const int hh = hh0 + dd;
        float gi = sacc[0 * 4 + dd][b] + bih[hh]           + bhh[hh];
        float gf = sacc[1 * 4 + dd][b] + bih[512 + hh]     + bhh[512 + hh];
        float gg = sacc[2 * 4 + dd][b] + bih[1024 + hh]    + bhh[1024 + hh];
        float go = sacc[3 * 4 + dd][b] + bih[1536 + hh]    + bhh[1536 + hh];
        float c  = g_c[b * HHD + hh];
        float cn = sigm(gf) * c + sigm(gi) * tanhf(gg);
        float hn = sigm(go) * tanhf(cn);
        g_c[b * HHD + hh] = cn;
        g_h[sel ^ 1][b * HHD + hh] = hn;
    }
}

// ========== K2: out+keys GEMM with fused finish epilogue + argmin ===========
// grid (8 j-groups, 32 batch-pairs) x 256 threads.
//   jg 0,1  -> out rows (bias bout)
//   jg 2..5 -> read key r=jg-2: add bkey, L2-normalize, write g_Kn
//   jg 6    -> write key: add bkey, write g_wkey
//   jg 7    -> argmin(usage) for the 2 batches + zero read_vec
__global__ void __launch_bounds__(256) k_ok2(
    const float* __restrict__ Wout, const float* __restrict__ Wkey,
    const float* __restrict__ bout, const float* __restrict__ bkey,
    float* __restrict__ out, int t, int sel)
{
    __shared__ __align__(16) float4 hs[2][128];   // 2 batches x 512 floats
    __shared__ float ys[2][64];
    __shared__ float sinv[2];
    __shared__ float asv[256];
    __shared__ int   asi[256];

    const int tid  = threadIdx.x;
    const int wid  = tid >> 5, lane = tid & 31;
    const int jg   = blockIdx.x;
    const int b0   = blockIdx.y * 2;

    if (jg == 7) {
        const int half = tid >> 7;
        const int ht   = tid & 127;
        const int b    = b0 + half;
        float bv = 3.4e38f; int bi = 0;
        for (int i = ht; i < NND; i += 128) {
            float u = g_usage[b * NND + i];
            if (u < bv) { bv = u; bi = i; }
        }
        asv[tid] = bv; asi[tid] = bi;
        __syncthreads();
        for (int s = 64; s; s >>= 1) {
            if (ht < s) {
                float ov = asv[tid + s]; int oi = asi[tid + s];
                if (ov < asv[tid] || (ov == asv[tid] && oi < asi[tid])) {
                    asv[tid] = ov; asi[tid] = oi;
                }
            }
            __syncthreads();
        }
        if (ht == 0) g_lu[b] = asi[tid];
        g_read_vec[b * RRD * WWD + ht]       = 0.f;
        g_read_vec[b * RRD * WWD + ht + 128] = 0.f;
        return;
    }

    const int j0 = jg * 64;
    const float* __restrict__ hn = g_h[sel ^ 1];

    {
        int bb = tid >> 7, idx = tid & 127;
        hs[bb][idx] = ((const float4*)(hn + (size_t)(b0 + bb) * HHD))[idx];
    }
    __syncthreads();

#pragma unroll 2
    for (int jj = 0; jj < 8; ++jj) {
        int j = j0 + wid * 8 + jj;
        const float* wrow = (j < OUTW) ? (Wout + (size_t)j * HHD)
                                       : (Wkey + (size_t)(j - OUTW) * HHD);
        const float4* w4 = (const float4*)wrow;
        float s0 = 0.f, s1 = 0.f;
#pragma unroll
        for (int it = 0; it < 4; ++it) {
            float4 w = w4[lane + 32 * it];
            float4 h0 = hs[0][lane + 32 * it];
            float4 h1 = hs[1][lane + 32 * it];
            s0 += w.x * h0.x + w.y * h0.y + w.z * h0.z + w.w * h0.w;
            s1 += w.x * h1.x + w.y * h1.y + w.z * h1.z + w.w * h1.w;
        }
#pragma unroll
        for (int o = 16; o; o >>= 1) {
            s0 += __shfl_xor_sync(0xffffffffu, s0, o);
            s1 += __shfl_xor_sync(0xffffffffu, s1, o);
        }
        if (lane == 0) { ys[0][wid * 8 + jj] = s0; ys[1][wid * 8 + jj] = s1; }
    }
    __syncthreads();

    if (jg < 2) {
        if (tid < 128) {
            int bb = tid >> 6, jj = tid & 63;
            out[(size_t)t * BB * OUTW + (size_t)(b0 + bb) * OUTW + j0 + jj] =
                ys[bb][jj] + bout[j0 + jj];
        }
    } else if (jg == 6) {
        if (tid < 128) {
            int bb = tid >> 6, jj = tid & 63;
            g_wkey[(b0 + bb) * WWD + jj] = ys[bb][jj] + bkey[4 * 64 + jj];
        }
    } else {
        const int kb = (jg - 2) * 64;
        if (tid < 128) {
            int bb = tid >> 6, jj = tid & 63;
            ys[bb][jj] += bkey[kb + jj];
        }
        __syncthreads();
        if (wid < 2) {
            float v0 = ys[wid][lane];
            float v1 = ys[wid][lane + 32];
            float ss = v0 * v0 + v1 * v1;
#pragma unroll
            for (int o = 16; o; o >>= 1) ss += __shfl_xor_sync(0xffffffffu, ss, o);
            if (lane == 0) sinv[wid] = 1.f / (sqrtf(ss) + EPSF);
        }
        __syncthreads();
        if (tid < 128) {
            int bb = tid >> 6, jj = tid & 63;
            g_Kn[(b0 + bb) * (RRD * WWD) + kb + jj] = ys[bb][jj] * sinv[bb];
        }
    }
}

// ==================== K3: sim + online softmax stats ========================
// grid (32, BB) x 64 threads, 16 blocks/SM. Two w-phases of 32 (tile 8.4 KB).
// Each thread privately reduces one M-row; 2 warps emit 4 chunk stats.
__global__ void __launch_bounds__(64, 16) k_sim() {
    __shared__ float tile[64 * 33];                  // 8.4 KB
    __shared__ __align__(16) float s_kn[RRD * WWD];  // 1 KB
    __shared__ float s_sv[4][64];                    // 1 KB

    const int b    = blockIdx.y;
    const int nb   = blockIdx.x;     // 32 chunks x 64 rows
    const int tid  = threadIdx.x;    // 64
    const int wid  = tid >> 5, lane = tid & 31;

#pragma unroll
    for (int i = 0; i < 4; ++i)
        s_kn[tid + 64 * i] = g_Kn[b * RRD * WWD + tid + 64 * i];

    const float4* Mb = (const float4*)(g_M + ((size_t)b * NND + nb * 64) * WWD);

    float ss = 0.f, d0 = 0.f, d1 = 0.f, d2 = 0.f, d3 = 0.f;

#pragma unroll
    for (int p = 0; p < 2; ++p) {
        __syncthreads();
        // stage half tile: 64 rows x 32 floats (8 float4 per thread, coalesced)
#pragma unroll
        for (int i = 0; i < 8; ++i) {
            int fid = tid + 64 * i;
            int row = fid >> 3, c4 = fid & 7;
            float4 v = Mb[row * 16 + p * 8 + c4];
            float* dst = tile + row * 33 + c4 * 4;
            dst[0] = v.x; dst[1] = v.y; dst[2] = v.z; dst[3] = v.w;
        }
        __syncthreads();
        const float* tr = tile + tid * 33;
        const float4* kk0 = (const float4*)(s_kn + 0 * 64 + p * 32);
        const float4* kk1 = (const float4*)(s_kn + 1 * 64 + p * 32);
        const float4* kk2 = (const float4*)(s_kn + 2 * 64 + p * 32);
        const float4* kk3 = (const float4*)(s_kn + 3 * 64 + p * 32);
#pragma unroll
        for (int w4 = 0; w4 < 8; ++w4) {
            float m0 = tr[w4 * 4 + 0];
            float m1 = tr[w4 * 4 + 1];
            float m2 = tr[w4 * 4 + 2];
            float m3 = tr[w4 * 4 + 3];
            float4 a = kk0[w4], bb = kk1[w4], c = kk2[w4], d = kk3[w4];
            ss += m0 * m0 + m1 * m1 + m2 * m2 + m3 * m3;
            d0 += m0 * a.x + m1 * a.y + m2 * a.z + m3 * a.w;
            d1 += m0 * bb.x + m1 * bb.y + m2 * bb.z + m3 * bb.w;
            d2 += m0 * c.x + m1 * c.y + m2 * c.z + m3 * c.w;
            d3 += m0 * d.x + m1 * d.y + m2 * d.z + m3 * d.w;
        }
    }

    float inv = 1.f / (sqrtf(ss) + EPSF);
    float s0 = d0 * inv, s1 = d1 * inv, s2 = d2 * inv, s3 = d3 * inv;
    const int n = nb * 64 + tid;
    g_sim[(size_t)(b * RRD + 0) * NND + n] = s0;
    g_sim[(size_t)(b * RRD + 1) * NND + n] = s1;
    g_sim[(size_t)(b * RRD + 2) * NND + n] = s2;
    g_sim[(size_t)(b * RRD + 3) * NND + n] = s3;
    s_sv[0][tid] = s0; s_sv[1][tid] = s1; s_sv[2][tid] = s2; s_sv[3][tid] = s3;
    __syncthreads();

    // 2 warps x 2 r each: chunk (max, sumexp)
#pragma unroll
    for (int rr = 0; rr < 2; ++rr) {
        int r = wid * 2 + rr;
        float v0 = s_sv[r][lane];
        float v1 = s_sv[r][lane + 32];
        float m = fmaxf(v0, v1);
#pragma unroll
        for (int o = 16; o; o >>= 1) m = fmaxf(m, __shfl_xor_sync(0xffffffffu, m, o));
        float S = expf(v0 - m) + expf(v1 - m);
#pragma unroll
        for (int o = 16; o; o >>= 1) S += __shfl_xor_sync(0xffffffffu, S, o);
        if (lane == 0)
            g_stats[(b * RRD + r) * NCHUNK + nb] = make_float2(m, S);
    }
}

// ==================== K4: memory update (softmax fused in) ==================
// grid (16, BB) x 256. Prologue: combine 32 chunk stats per r, compute
// rw_new for this block's 128 rows into smem (+ write to g_rw[sel]),
// stage sum(rw_old) and sum(rw_new) per row. Main pass over M is then
// 1 LDG + 1 STG + LDS broadcasts per row.
__global__ void __launch_bounds__(256) k_update(int sel,
                                                const float* __restrict__ alpha,
                                                const float* __restrict__ gamma) {
    const int b   = blockIdx.y;
    const int cx  = blockIdx.x;       // 16 chunks x 128 n
    const int tid = threadIdx.x, wid = tid >> 5, lane = tid & 31;
    const float* __restrict__ rw_old = g_rw[sel ^ 1];
    float* __restrict__ rw_out = g_rw[sel];
    const float sa = 1.f / (1.f + expf(-alpha[0]));
    const float gm = gamma[0];
    const int lu = g_lu[b];

    __shared__ __align__(16) float wk[WWD];
    __shared__ float2 s_st[4 * NCHUNK];
    __shared__ float s_m[4], s_is[4];
    __shared__ float srw[4][128];
    __shared__ float s_so[128], s_sn[128];

    if (tid < 128) s_st[tid] = g_stats[(b * RRD + (tid >> 5)) * NCHUNK + (tid & 31)];
    else if (tid < 192) wk[tid - 128] = g_wkey[b * WWD + (tid - 128)];
    __syncthreads();
    if (tid < 4) {
        float m = -3.4e38f;
#pragma unroll
        for (int i = 0; i < NCHUNK; ++i) m = fmaxf(m, s_st[tid * NCHUNK + i].x);
        float S = 0.f;
#pragma unroll
        for (int i = 0; i < NCHUNK; ++i) {
            float2 p = s_st[tid * NCHUNK + i];
            S += p.y * expf(p.x - m);
        }
        s_m[tid] = m; s_is[tid] = 1.f / S;
    }
    __syncthreads();

    const int n0 = cx * 128;
#pragma unroll
    for (int k2 = 0; k2 < 2; ++k2) {
        int idx = tid + 256 * k2;
        int r = idx >> 7, nl = idx & 127;
        float sv = g_sim[(size_t)(b * RRD + r) * NND + n0 + nl];
        float e = expf(sv - s_m[r]) * s_is[r];
        srw[r][nl] = e;
        rw_out[(size_t)(b * RRD + r) * NND + n0 + nl] = e;
    }
    __syncthreads();

    if (tid < 128) {
        float so = 0.f;
#pragma unroll
        for (int r = 0; r < 4; ++r)
            so += rw_old[(size_t)(b * RRD + r) * NND + n0 + tid];
        s_so[tid] = so;
        s_sn[tid] = srw[0][tid] + srw[1][tid] + srw[2][tid] + srw[3][tid];
    }
    __syncthreads();

    const float2 wk2 = ((const float2*)wk)[lane];

    float2 a0 = {0.f, 0.f}, a1 = {0.f, 0.f}, a2 = {0.f, 0.f}, a3 = {0.f, 0.f};
#pragma unroll 8
    for (int i = 0; i < 16; ++i) {
        int nl = wid * 16 + i;
        int n  = n0 + nl;
        size_t moff = (size_t)(b * NND + n) * WWD;
        float2 m = ((const float2*)(g_M + moff))[lane];
        float r0 = srw[0][nl];
        float r1 = srw[1][nl];
        float r2 = srw[2][nl];
        float r3 = srw[3][nl];
        float so = s_so[nl];
        bool is_lu = (n == lu);
        float ww = sa * so + (is_lu ? (1.f - sa) : 0.f);
        float2 mn;
        mn.x = (is_lu ? 0.f : m.x) + ww * wk2.x;
        mn.y = (is_lu ? 0.f : m.y) + ww * wk2.y;
        ((float2*)(g_M + moff))[lane] = mn;
        // read_vec uses OLD M
        a0.x += r0 * m.x; a0.y += r0 * m.y;
        a1.x += r1 * m.x; a1.y += r1 * m.y;
        a2.x += r2 * m.x; a2.y += r2 * m.y;
        a3.x += r3 * m.x; a3.y += r3 * m.y;
        if (lane == 0)
            g_usage[b * NND + n] = gm * g_usage[b * NND + n] + s_sn[nl] + ww;
    }
    // cross-warp reduce into read_vec
    __shared__ float red[8][RRD * WWD];
    float* rp = red[wid];
    rp[0 * WWD + 2 * lane] = a0.x; rp[0 * WWD + 2 * lane + 1] = a0.y;
    rp[1 * WWD + 2 * lane] = a1.x; rp[1 * WWD + 2 * lane + 1] = a1.y;
    rp[2 * WWD + 2 * lane] = a2.x; rp[2 * WWD + 2 * lane + 1] = a2.y;
    rp[3 * WWD + 2 * lane] = a3.x; rp[3 * WWD + 2 * lane + 1] = a3.y;
    __syncthreads();
    if (tid < RRD * WWD) {
        float s = 0.f;
#pragma unroll
        for (int w = 0; w < 8; ++w) s += red[w][tid];
        atomicAdd(&g_read_vec[b * RRD * WWD + tid], s);
    }
}

// ------------------------------- launcher ------------------------------------
extern "C" void kernel_launch(void* const* d_in, const int* in_sizes, int n_in,
                              void* d_out, int out_size) {
    const float* x_seq = (const float*)d_in[0];
    const float* Wih   = (const float*)d_in[1];
    const float* Whh   = (const float*)d_in[2];
    const float* bih   = (const float*)d_in[3];
    const float* bhh   = (const float*)d_in[4];
    const float* Wout  = (const float*)d_in[5];
    const float* bout  = (const float*)d_in[6];
    const float* Wkey  = (const float*)d_in[7];
    const float* bkey  = (const float*)d_in[8];
    const float* alpha = (const float*)d_in[9];
    const float* gamma = (const float*)d_in[10];
    float* out = (float*)d_out;

    k_reset<<<32768, 256>>>();

    for (int t = 0; t < TT; ++t) {
        const int sel = t & 1;
        k_gates<<<JGATE / 16, 256>>>(x_seq + (size_t)t * BB * INW,
                                     Wih, Whh, bih, bhh, sel);
        k_ok2<<<dim3(8, 32), 256>>>(Wout, Wkey, bout, bkey, out, t, sel);
        k_sim<<<dim3(NCHUNK, BB), 64>>>();
        k_update<<<dim3(16, BB), 256>>>(sel, alpha, gamma);
    }
}

// round 12
// speedup vs baseline: 1.1977x; 1.1977x over previous
#include <cuda_runtime.h>
#include <math.h>
#include <stdint.h>

// Problem constants
#define BB    64
#define TT    128
#define INW   128
#define HHD   512
#define NND   2048
#define WWD   64
#define OUTW  128
#define RRD   4
#define CTRL  384            // IN + R*W
#define KGATE 896            // CTRL + H  (14 tiles of 64)
#define JGATE 2048           // 4*H
#define JOK   448            // OUT + (R+1)*W
#define EPSF  1e-8f
#define NCHUNK 16            // sim/stats chunks per (b,r)

// ------------------------- persistent device state -------------------------
__device__ float g_h[2][BB * HHD];             // ping-pong hidden state
__device__ float g_c[BB * HHD];
__device__ float g_M[BB * NND * WWD];          // 33.5 MB
__device__ float g_usage[BB * NND];
__device__ float g_rw[2][BB * RRD * NND];      // ping-pong read weights
__device__ float g_read_vec[BB * RRD * WWD];
__device__ float g_sim[BB * RRD * NND];        // raw cosine sims
__device__ float2 g_stats[BB * RRD * NCHUNK];  // per-chunk (max, sumexp)
__device__ float g_Kn[BB * RRD * WWD];         // normalized read keys
__device__ float g_wkey[BB * WWD];             // write key
__device__ int   g_lu[BB];                     // argmin(usage) per batch

// ------------------------------- reset -------------------------------------
__global__ void k_reset() {
    long idx = (long)blockIdx.x * blockDim.x + threadIdx.x;
    if (idx < (long)BB * NND * WWD) g_M[idx] = 1e-6f;
    if (idx < BB * HHD) { g_h[0][idx] = 0.f; g_h[1][idx] = 0.f; g_c[idx] = 0.f; }
    if (idx < BB * NND) g_usage[idx] = 0.f;
    if (idx < BB * RRD * NND) { g_rw[0][idx] = 0.f; g_rw[1][idx] = 0.f; }
    if (idx < BB * RRD * WWD) g_read_vec[idx] = 0.f;
    if (idx < BB) g_lu[idx] = 0;
}

__device__ __forceinline__ float sigm(float x) { return 1.f / (1.f + expf(-x)); }

// ==================== K1: gates GEMM + LSTM epilogue ========================
// grid 128 blocks x 256 threads. Block bid owns hh0 = bid*4: the 4 hidden
// units hh0..hh0+3 across ALL 4 gates (16 j values), all 64 batches, full K.
// Register double-buffering: tile t+1 loads overlap tile t compute.
__global__ void __launch_bounds__(256) k_gates(
    const float* __restrict__ xt,
    const float* __restrict__ Wih, const float* __restrict__ Whh,
    const float* __restrict__ bih, const float* __restrict__ bhh,
    int sel)
{
    __shared__ __align__(16) float4 xs4[BB * 16];   // 64 b x 64 k = 16 KB
    __shared__ __align__(16) float4 ws4[16 * 17];   // 16 j x 64 k padded
    __shared__ float sacc[16][BB];                  // acc staging, 4 KB

    const int tid = threadIdx.x;
    const int hq  = tid & 15;       // jj
    const int bq  = tid >> 4;       // 16 batch quads
    const int hh0 = blockIdx.x * 4;
    const float* __restrict__ hr = g_h[sel];

    const int xb   = tid >> 4;
    const int xk4  = tid & 15;
    const int wr_r = tid >> 4;
    const int jr   = hh0 + (wr_r & 3) + (wr_r >> 2) * 512;

    float acc[4] = {0.f, 0.f, 0.f, 0.f};

    float4 xreg[4];
    float4 wreg;

    // prologue: load tile 0 into registers
    {
        const int k0 = 0;
#pragma unroll
        for (int li = 0; li < 4; ++li) {
            int b = xb + 16 * li;
            int k = k0 + xk4 * 4;
            const float* src;
            if (k < INW)       src = xt + b * INW + k;
            else if (k < CTRL) src = g_read_vec + b * (RRD * WWD) + (k - INW);
            else               src = hr + b * HHD + (k - CTRL);
            xreg[li] = *reinterpret_cast<const float4*>(src);
        }
        int k = k0 + xk4 * 4;
        const float* src = (k < CTRL) ? (Wih + (size_t)jr * CTRL + k)
                                      : (Whh + (size_t)jr * HHD + (k - CTRL));
        wreg = *reinterpret_cast<const float4*>(src);
    }

    for (int tl = 0; tl < 14; ++tl) {
#pragma unroll
        for (int li = 0; li < 4; ++li)
            xs4[(xb + 16 * li) * 16 + xk4] = xreg[li];
        ws4[wr_r * 17 + xk4] = wreg;
        __syncthreads();

        if (tl + 1 < 14) {
            const int k0 = (tl + 1) * 64;
#pragma unroll
            for (int li = 0; li < 4; ++li) {
                int b = xb + 16 * li;
                int k = k0 + xk4 * 4;
                const float* src;
                if (k < INW)       src = xt + b * INW + k;
                else if (k < CTRL) src = g_read_vec + b * (RRD * WWD) + (k - INW);
                else               src = hr + b * HHD + (k - CTRL);
                xreg[li] = *reinterpret_cast<const float4*>(src);
            }
            int k = k0 + xk4 * 4;
            const float* src = (k < CTRL) ? (Wih + (size_t)jr * CTRL + k)
                                          : (Whh + (size_t)jr * HHD + (k - CTRL));
            wreg = *reinterpret_cast<const float4*>(src);
        }

#pragma unroll
        for (int kk = 0; kk < 16; ++kk) {
            float4 wv = ws4[hq * 17 + kk];
#pragma unroll
            for (int i = 0; i < 4; ++i) {
                float4 xv = xs4[(bq * 4 + i) * 16 + kk];
                acc[i] += xv.x * wv.x + xv.y * wv.y + xv.z * wv.z + xv.w * wv.w;
            }
        }
        __syncthreads();
    }

#pragma unroll
    for (int i = 0; i < 4; ++i) sacc[hq][bq * 4 + i] = acc[i];
    __syncthreads();

    {
        const int b  = tid & 63;
        const int dd = tid >> 6;
        const int hh = hh0 + dd;
        float gi = sacc[0 * 4 + dd][b] + bih[hh]           + bhh[hh];
        float gf = sacc[1 * 4 + dd][b] + bih[512 + hh]     + bhh[512 + hh];
        float gg = sacc[2 * 4 + dd][b] + bih[1024 + hh]    + bhh[1024 + hh];
        float go = sacc[3 * 4 + dd][b] + bih[1536 + hh]    + bhh[1536 + hh];
        float c  = g_c[b * HHD + hh];
        float cn = sigm(gf) * c + sigm(gi) * tanhf(gg);
        float hn = sigm(go) * tanhf(cn);
        g_c[b * HHD + hh] = cn;
        g_h[sel ^ 1][b * HHD + hh] = hn;
    }
}

// ========== K2: out+keys GEMM with fused finish epilogue + argmin ===========
// grid (8 j-groups, 32 batch-pairs) x 256 threads.
//   jg 0,1  -> out rows (bias bout)
//   jg 2..5 -> read key r=jg-2: add bkey, L2-normalize, write g_Kn
//   jg 6    -> write key: add bkey, write g_wkey
//   jg 7    -> argmin(usage) for the 2 batches + zero read_vec
__global__ void __launch_bounds__(256) k_ok2(
    const float* __restrict__ Wout, const float* __restrict__ Wkey,
    const float* __restrict__ bout, const float* __restrict__ bkey,
    float* __restrict__ out, int t, int sel)
{
    __shared__ __align__(16) float4 hs[2][128];   // 2 batches x 512 floats
    __shared__ float ys[2][64];
    __shared__ float sinv[2];
    __shared__ float asv[256];
    __shared__ int   asi[256];

    const int tid  = threadIdx.x;
    const int wid  = tid >> 5, lane = tid & 31;
    const int jg   = blockIdx.x;
    const int b0   = blockIdx.y * 2;

    if (jg == 7) {
        const int half = tid >> 7;
        const int ht   = tid & 127;
        const int b    = b0 + half;
        float bv = 3.4e38f; int bi = 0;
        for (int i = ht; i < NND; i += 128) {
            float u = g_usage[b * NND + i];
            if (u < bv) { bv = u; bi = i; }
        }
        asv[tid] = bv; asi[tid] = bi;
        __syncthreads();
        for (int s = 64; s; s >>= 1) {
            if (ht < s) {
                float ov = asv[tid + s]; int oi = asi[tid + s];
                if (ov < asv[tid] || (ov == asv[tid] && oi < asi[tid])) {
                    asv[tid] = ov; asi[tid] = oi;
                }
            }
            __syncthreads();
        }
        if (ht == 0) g_lu[b] = asi[tid];
        g_read_vec[b * RRD * WWD + ht]       = 0.f;
        g_read_vec[b * RRD * WWD + ht + 128] = 0.f;
        return;
    }

    const int j0 = jg * 64;
    const float* __restrict__ hn = g_h[sel ^ 1];

    {
        int bb = tid >> 7, idx = tid & 127;
        hs[bb][idx] = ((const float4*)(hn + (size_t)(b0 + bb) * HHD))[idx];
    }
    __syncthreads();

#pragma unroll 2
    for (int jj = 0; jj < 8; ++jj) {
        int j = j0 + wid * 8 + jj;
        const float* wrow = (j < OUTW) ? (Wout + (size_t)j * HHD)
                                       : (Wkey + (size_t)(j - OUTW) * HHD);
        const float4* w4 = (const float4*)wrow;
        float s0 = 0.f, s1 = 0.f;
#pragma unroll
        for (int it = 0; it < 4; ++it) {
            float4 w = w4[lane + 32 * it];
            float4 h0 = hs[0][lane + 32 * it];
            float4 h1 = hs[1][lane + 32 * it];
            s0 += w.x * h0.x + w.y * h0.y + w.z * h0.z + w.w * h0.w;
            s1 += w.x * h1.x + w.y * h1.y + w.z * h1.z + w.w * h1.w;
        }
#pragma unroll
        for (int o = 16; o; o >>= 1) {
            s0 += __shfl_xor_sync(0xffffffffu, s0, o);
            s1 += __shfl_xor_sync(0xffffffffu, s1, o);
        }
        if (lane == 0) { ys[0][wid * 8 + jj] = s0; ys[1][wid * 8 + jj] = s1; }
    }
    __syncthreads();

    if (jg < 2) {
        if (tid < 128) {
            int bb = tid >> 6, jj = tid & 63;
            out[(size_t)t * BB * OUTW + (size_t)(b0 + bb) * OUTW + j0 + jj] =
                ys[bb][jj] + bout[j0 + jj];
        }
    } else if (jg == 6) {
        if (tid < 128) {
            int bb = tid >> 6, jj = tid & 63;
            g_wkey[(b0 + bb) * WWD + jj] = ys[bb][jj] + bkey[4 * 64 + jj];
        }
    } else {
        const int kb = (jg - 2) * 64;
        if (tid < 128) {
            int bb = tid >> 6, jj = tid & 63;
            ys[bb][jj] += bkey[kb + jj];
        }
        __syncthreads();
        if (wid < 2) {
            float v0 = ys[wid][lane];
            float v1 = ys[wid][lane + 32];
            float ss = v0 * v0 + v1 * v1;
#pragma unroll
            for (int o = 16; o; o >>= 1) ss += __shfl_xor_sync(0xffffffffu, ss, o);
            if (lane == 0) sinv[wid] = 1.f / (sqrtf(ss) + EPSF);
        }
        __syncthreads();
        if (tid < 128) {
            int bb = tid >> 6, jj = tid & 63;
            g_Kn[(b0 + bb) * (RRD * WWD) + kb + jj] = ys[bb][jj] * sinv[bb];
        }
    }
}

// ==================== K3: sim + online softmax stats ========================
// grid (16, BB) x 128 threads, 8 blocks/SM. Two w-phases of 32 (tile 17 KB).
// Each thread privately reduces one M-row (zero shuffles in the main path),
// then one warp per r computes the chunk's (max, sumexp) -> g_stats.
__global__ void __launch_bounds__(128, 8) k_sim() {
    __shared__ float tile[128 * 33];                 // 16.9 KB
    __shared__ __align__(16) float s_kn[RRD * WWD];  // 1 KB
    __shared__ float s_sv[4][128];                   // 2 KB

    const int b    = blockIdx.y;
    const int nb   = blockIdx.x;     // 16 chunks x 128 rows
    const int tid  = threadIdx.x;    // 128
    const int wid  = tid >> 5, lane = tid & 31;

    s_kn[tid]       = g_Kn[b * RRD * WWD + tid];
    s_kn[tid + 128] = g_Kn[b * RRD * WWD + tid + 128];

    const float4* Mb = (const float4*)(g_M + ((size_t)b * NND + nb * 128) * WWD);

    float ss = 0.f, d0 = 0.f, d1 = 0.f, d2 = 0.f, d3 = 0.f;

#pragma unroll
    for (int p = 0; p < 2; ++p) {
        __syncthreads();
#pragma unroll
        for (int i = 0; i < 8; ++i) {
            int fid = tid + 128 * i;
            int row = fid >> 3, c4 = fid & 7;
            float4 v = Mb[row * 16 + p * 8 + c4];
            float* dst = tile + row * 33 + c4 * 4;
            dst[0] = v.x; dst[1] = v.y; dst[2] = v.z; dst[3] = v.w;
        }
        __syncthreads();
        const float* tr = tile + tid * 33;
        const float4* kk0 = (const float4*)(s_kn + 0 * 64 + p * 32);
        const float4* kk1 = (const float4*)(s_kn + 1 * 64 + p * 32);
        const float4* kk2 = (const float4*)(s_kn + 2 * 64 + p * 32);
        const float4* kk3 = (const float4*)(s_kn + 3 * 64 + p * 32);
#pragma unroll
        for (int w4 = 0; w4 < 8; ++w4) {
            float m0 = tr[w4 * 4 + 0];
            float m1 = tr[w4 * 4 + 1];
            float m2 = tr[w4 * 4 + 2];
            float m3 = tr[w4 * 4 + 3];
            float4 a = kk0[w4], bb = kk1[w4], c = kk2[w4], d = kk3[w4];
            ss += m0 * m0 + m1 * m1 + m2 * m2 + m3 * m3;
            d0 += m0 * a.x + m1 * a.y + m2 * a.z + m3 * a.w;
            d1 += m0 * bb.x + m1 * bb.y + m2 * bb.z + m3 * bb.w;
            d2 += m0 * c.x + m1 * c.y + m2 * c.z + m3 * c.w;
            d3 += m0 * d.x + m1 * d.y + m2 * d.z + m3 * d.w;
        }
    }

    float inv = 1.f / (sqrtf(ss) + EPSF);
    float s0 = d0 * inv, s1 = d1 * inv, s2 = d2 * inv, s3 = d3 * inv;
    const int n = nb * 128 + tid;
    g_sim[(size_t)(b * RRD + 0) * NND + n] = s0;
    g_sim[(size_t)(b * RRD + 1) * NND + n] = s1;
    g_sim[(size_t)(b * RRD + 2) * NND + n] = s2;
    g_sim[(size_t)(b * RRD + 3) * NND + n] = s3;
    s_sv[0][tid] = s0; s_sv[1][tid] = s1; s_sv[2][tid] = s2; s_sv[3][tid] = s3;
    __syncthreads();

    // warp wid: chunk stats for r = wid
    {
        float v0 = s_sv[wid][lane];
        float v1 = s_sv[wid][lane + 32];
        float v2 = s_sv[wid][lane + 64];
        float v3 = s_sv[wid][lane + 96];
        float m = fmaxf(fmaxf(v0, v1), fmaxf(v2, v3));
#pragma unroll
        for (int o = 16; o; o >>= 1) m = fmaxf(m, __shfl_xor_sync(0xffffffffu, m, o));
        float S = expf(v0 - m) + expf(v1 - m) + expf(v2 - m) + expf(v3 - m);
#pragma unroll
        for (int o = 16; o; o >>= 1) S += __shfl_xor_sync(0xffffffffu, S, o);
        if (lane == 0)
            g_stats[(b * RRD + wid) * NCHUNK + nb] = make_float2(m, S);
    }
}

// ==================== K4: memory update (softmax fused, de-LDG) =============
// grid (16, BB) x 256. Prologue: combine 16 chunk stats per r, compute
// rw_new for this block's 128 rows into smem (+ write to g_rw[sel]),
// stage sum(rw_old) and sum(rw_new) per row. Main pass over M is then
// 1 LDG + 1 STG + LDS broadcasts per row.
__global__ void __launch_bounds__(256) k_update(int sel,
                                                const float* __restrict__ alpha,
                                                const float* __restrict__ gamma) {
    const int b   = blockIdx.y;
    const int cx  = blockIdx.x;       // 16 chunks x 128 n
    const int tid = threadIdx.x, wid = tid >> 5, lane = tid & 31;
    const float* __restrict__ rw_old = g_rw[sel ^ 1];
    float* __restrict__ rw_out = g_rw[sel];
    const float sa = 1.f / (1.f + expf(-alpha[0]));
    const float gm = gamma[0];
    const int lu = g_lu[b];

    __shared__ __align__(16) float wk[WWD];
    __shared__ float2 s_st[4 * NCHUNK];
    __shared__ float s_m[4], s_is[4];
    __shared__ float srw[4][128];
    __shared__ float s_so[128], s_sn[128];

    if (tid < 64) s_st[tid] = g_stats[(b * RRD + (tid >> 4)) * NCHUNK + (tid & 15)];
    else if (tid < 128) wk[tid - 64] = g_wkey[b * WWD + (tid - 64)];
    __syncthreads();
    if (tid < 4) {
        float m = -3.4e38f;
#pragma unroll
        for (int i = 0; i < NCHUNK; ++i) m = fmaxf(m, s_st[tid * NCHUNK + i].x);
        float S = 0.f;
#pragma unroll
        for (int i = 0; i < NCHUNK; ++i) {
            float2 p = s_st[tid * NCHUNK + i];
            S += p.y * expf(p.x - m);
        }
        s_m[tid] = m; s_is[tid] = 1.f / S;
    }
    __syncthreads();

    const int n0 = cx * 128;
#pragma unroll
    for (int k2 = 0; k2 < 2; ++k2) {
        int idx = tid + 256 * k2;
        int r = idx >> 7, nl = idx & 127;
        float sv = g_sim[(size_t)(b * RRD + r) * NND + n0 + nl];
        float e = expf(sv - s_m[r]) * s_is[r];
        srw[r][nl] = e;
        rw_out[(size_t)(b * RRD + r) * NND + n0 + nl] = e;
    }
    __syncthreads();

    if (tid < 128) {
        float so = 0.f;
#pragma unroll
        for (int r = 0; r < 4; ++r)
            so += rw_old[(size_t)(b * RRD + r) * NND + n0 + tid];
        s_so[tid] = so;
        s_sn[tid] = srw[0][tid] + srw[1][tid] + srw[2][tid] + srw[3][tid];
    }
    __syncthreads();

    const float2 wk2 = ((const float2*)wk)[lane];

    float2 a0 = {0.f, 0.f}, a1 = {0.f, 0.f}, a2 = {0.f, 0.f}, a3 = {0.f, 0.f};
#pragma unroll 8
    for (int i = 0; i < 16; ++i) {
        int nl = wid * 16 + i;
        int n  = n0 + nl;
        size_t moff = (size_t)(b * NND + n) * WWD;
        float2 m = ((const float2*)(g_M + moff))[lane];
        float r0 = srw[0][nl];
        float r1 = srw[1][nl];
        float r2 = srw[2][nl];
        float r3 = srw[3][nl];
        float so = s_so[nl];
        bool is_lu = (n == lu);
        float ww = sa * so + (is_lu ? (1.f - sa) : 0.f);
        float2 mn;
        mn.x = (is_lu ? 0.f : m.x) + ww * wk2.x;
        mn.y = (is_lu ? 0.f : m.y) + ww * wk2.y;
        ((float2*)(g_M + moff))[lane] = mn;
        // read_vec uses OLD M
        a0.x += r0 * m.x; a0.y += r0 * m.y;
        a1.x += r1 * m.x; a1.y += r1 * m.y;
        a2.x += r2 * m.x; a2.y += r2 * m.y;
        a3.x += r3 * m.x; a3.y += r3 * m.y;
        if (lane == 0)
            g_usage[b * NND + n] = gm * g_usage[b * NND + n] + s_sn[nl] + ww;
    }
    // cross-warp reduce into read_vec
    __shared__ float red[8][RRD * WWD];
    float* rp = red[wid];
    rp[0 * WWD + 2 * lane] = a0.x; rp[0 * WWD + 2 * lane + 1] = a0.y;
    rp[1 * WWD + 2 * lane] = a1.x; rp[1 * WWD + 2 * lane + 1] = a1.y;
    rp[2 * WWD + 2 * lane] = a2.x; rp[2 * WWD + 2 * lane + 1] = a2.y;
    rp[3 * WWD + 2 * lane] = a3.x; rp[3 * WWD + 2 * lane + 1] = a3.y;
    __syncthreads();
    if (tid < RRD * WWD) {
        float s = 0.f;
#pragma unroll
        for (int w = 0; w < 8; ++w) s += red[w][tid];
        atomicAdd(&g_read_vec[b * RRD * WWD + tid], s);
    }
}

// ------------------------------- launcher ------------------------------------
extern "C" void kernel_launch(void* const* d_in, const int* in_sizes, int n_in,
                              void* d_out, int out_size) {
    const float* x_seq = (const float*)d_in[0];
    const float* Wih   = (const float*)d_in[1];
    const float* Whh   = (const float*)d_in[2];
    const float* bih   = (const float*)d_in[3];
    const float* bhh   = (const float*)d_in[4];
    const float* Wout  = (const float*)d_in[5];
    const float* bout  = (const float*)d_in[6];
    const float* Wkey  = (const float*)d_in[7];
    const float* bkey  = (const float*)d_in[8];
    const float* alpha = (const float*)d_in[9];
    const float* gamma = (const float*)d_in[10];
    float* out = (float*)d_out;

    k_reset<<<32768, 256>>>();

    for (int t = 0; t < TT; ++t) {
        const int sel = t & 1;
        k_gates<<<JGATE / 16, 256>>>(x_seq + (size_t)t * BB * INW,
                                     Wih, Whh, bih, bhh, sel);
        k_ok2<<<dim3(8, 32), 256>>>(Wout, Wkey, bout, bkey, out, t, sel);
        k_sim<<<dim3(NCHUNK, BB), 128>>>();
        k_update<<<dim3(16, BB), 256>>>(sel, alpha, gamma);
    }
}

// round 13
// speedup vs baseline: 1.4299x; 1.1939x over previous
#include <cuda_runtime.h>
#include <math.h>
#include <stdint.h>

// Problem constants
#define BB    64
#define TT    128
#define INW   128
#define HHD   512
#define NND   2048
#define WWD   64
#define OUTW  128
#define RRD   4
#define CTRL  384            // IN + R*W
#define JGATE 2048           // 4*H
#define EPSF  1e-8f
#define NCHUNK 16            // sim/stats chunks per (b,r)

// ------------------------- persistent device state -------------------------
__device__ float g_h[2][BB * HHD];               // ping-pong hidden state
__device__ float g_c[BB * HHD];
__device__ float g_M[BB * NND * WWD];            // 33.5 MB
__device__ float g_usage[BB * NND];
__device__ float g_rwsum[2][BB * NND];           // ping-pong sum_r(read_w)
__device__ float g_read_vec[BB * RRD * WWD];
__device__ float g_sim[BB * RRD * NND];          // raw cosine sims
__device__ float2 g_stats[BB * RRD * NCHUNK];    // per-chunk (max, sumexp)
__device__ float g_P[NCHUNK * BB * RRD * WWD];   // chunk partials for read_vec
__device__ float g_Kn[BB * RRD * WWD];           // normalized read keys
__device__ float g_wkey[2][BB * WWD];            // ping-pong write key
__device__ int   g_lu[2][BB];                    // ping-pong argmin(usage)

// ------------------------------- reset -------------------------------------
__global__ void k_reset() {
    long idx = (long)blockIdx.x * blockDim.x + threadIdx.x;
    if (idx < (long)BB * NND * WWD) g_M[idx] = 1e-6f;
    if (idx < BB * HHD) { g_h[0][idx] = 0.f; g_h[1][idx] = 0.f; g_c[idx] = 0.f; }
    if (idx < BB * NND) { g_usage[idx] = 0.f; g_rwsum[0][idx] = 0.f; g_rwsum[1][idx] = 0.f; }
    if (idx < BB * RRD * WWD) g_read_vec[idx] = 0.f;
    if (idx < BB * WWD) { g_wkey[0][idx] = 0.f; g_wkey[1][idx] = 0.f; }
    if (idx < BB) { g_lu[0][idx] = 0; g_lu[1][idx] = 0; }
}

__device__ __forceinline__ float sigm(float x) { return 1.f / (1.f + expf(-x)); }

// ==================== K1: gates GEMM + LSTM epilogue ========================
// grid 128 blocks x 256 threads. Block bid owns hh0 = bid*4: the 4 hidden
// units hh0..hh0+3 across ALL 4 gates (16 j values), all 64 batches, full K.
// Register double-buffering: tile t+1 loads overlap tile t compute.
__global__ void __launch_bounds__(256) k_gates(
    const float* __restrict__ xt,
    const float* __restrict__ Wih, const float* __restrict__ Whh,
    const float* __restrict__ bih, const float* __restrict__ bhh,
    int sel)
{
    __shared__ __align__(16) float4 xs4[BB * 16];   // 64 b x 64 k = 16 KB
    __shared__ __align__(16) float4 ws4[16 * 17];   // 16 j x 64 k padded
    __shared__ float sacc[16][BB];                  // acc staging, 4 KB

    const int tid = threadIdx.x;
    const int hq  = tid & 15;       // jj
    const int bq  = tid >> 4;       // 16 batch quads
    const int hh0 = blockIdx.x * 4;
    const float* __restrict__ hr = g_h[sel];

    const int xb   = tid >> 4;
    const int xk4  = tid & 15;
    const int wr_r = tid >> 4;
    const int jr   = hh0 + (wr_r & 3) + (wr_r >> 2) * 512;

    float acc[4] = {0.f, 0.f, 0.f, 0.f};

    float4 xreg[4];
    float4 wreg;

    {
        const int k0 = 0;
#pragma unroll
        for (int li = 0; li < 4; ++li) {
            int b = xb + 16 * li;
            int k = k0 + xk4 * 4;
            const float* src;
            if (k < INW)       src = xt + b * INW + k;
            else if (k < CTRL) src = g_read_vec + b * (RRD * WWD) + (k - INW);
            else               src = hr + b * HHD + (k - CTRL);
            xreg[li] = *reinterpret_cast<const float4*>(src);
        }
        int k = k0 + xk4 * 4;
        const float* src = (k < CTRL) ? (Wih + (size_t)jr * CTRL + k)
                                      : (Whh + (size_t)jr * HHD + (k - CTRL));
        wreg = *reinterpret_cast<const float4*>(src);
    }

    for (int tl = 0; tl < 14; ++tl) {
#pragma unroll
        for (int li = 0; li < 4; ++li)
            xs4[(xb + 16 * li) * 16 + xk4] = xreg[li];
        ws4[wr_r * 17 + xk4] = wreg;
        __syncthreads();

        if (tl + 1 < 14) {
            const int k0 = (tl + 1) * 64;
#pragma unroll
            for (int li = 0; li < 4; ++li) {
                int b = xb + 16 * li;
                int k = k0 + xk4 * 4;
                const float* src;
                if (k < INW)       src = xt + b * INW + k;
                else if (k < CTRL) src = g_read_vec + b * (RRD * WWD) + (k - INW);
                else               src = hr + b * HHD + (k - CTRL);
                xreg[li] = *reinterpret_cast<const float4*>(src);
            }
            int k = k0 + xk4 * 4;
            const float* src = (k < CTRL) ? (Wih + (size_t)jr * CTRL + k)
                                          : (Whh + (size_t)jr * HHD + (k - CTRL));
            wreg = *reinterpret_cast<const float4*>(src);
        }

#pragma unroll
        for (int kk = 0; kk < 16; ++kk) {
            float4 wv = ws4[hq * 17 + kk];
#pragma unroll
            for (int i = 0; i < 4; ++i) {
                float4 xv = xs4[(bq * 4 + i) * 16 + kk];
                acc[i] += xv.x * wv.x + xv.y * wv.y + xv.z * wv.z + xv.w * wv.w;
            }
        }
        __syncthreads();
    }

#pragma unroll
    for (int i = 0; i < 4; ++i) sacc[hq][bq * 4 + i] = acc[i];
    __syncthreads();

    {
        const int b  = tid & 63;
        const int dd = tid >> 6;
        const int hh = hh0 + dd;
        float gi = sacc[0 * 4 + dd][b] + bih[hh]           + bhh[hh];
        float gf = sacc[1 * 4 + dd][b] + bih[512 + hh]     + bhh[512 + hh];
        float gg = sacc[2 * 4 + dd][b] + bih[1024 + hh]    + bhh[1024 + hh];
        float go = sacc[3 * 4 + dd][b] + bih[1536 + hh]    + bhh[1536 + hh];
        float c  = g_c[b * HHD + hh];
        float cn = sigm(gf) * c + sigm(gi) * tanhf(gg);
        float hn = sigm(go) * tanhf(cn);
        g_c[b * HHD + hh] = cn;
        g_h[sel ^ 1][b * HHD + hh] = hn;
    }
}

// ========== K2: out+keys GEMM with fused finish epilogue + argmin ===========
// grid (8 j-groups, 32 batch-pairs) x 256 threads.
//   jg 0,1  -> out rows (bias bout)
//   jg 2..5 -> read key r=jg-2: add bkey, L2-normalize, write g_Kn
//   jg 6    -> write key: add bkey, write g_wkey[t&1]
//   jg 7    -> argmin(usage) for the 2 batches -> g_lu[t&1]
__global__ void __launch_bounds__(256) k_ok2(
    const float* __restrict__ Wout, const float* __restrict__ Wkey,
    const float* __restrict__ bout, const float* __restrict__ bkey,
    float* __restrict__ out, int t, int sel)
{
    __shared__ __align__(16) float4 hs[2][128];   // 2 batches x 512 floats
    __shared__ float ys[2][64];
    __shared__ float sinv[2];
    __shared__ float asv[256];
    __shared__ int   asi[256];

    const int tid  = threadIdx.x;
    const int wid  = tid >> 5, lane = tid & 31;
    const int jg   = blockIdx.x;
    const int b0   = blockIdx.y * 2;

    if (jg == 7) {
        const int half = tid >> 7;
        const int ht   = tid & 127;
        const int b    = b0 + half;
        float bv = 3.4e38f; int bi = 0;
        for (int i = ht; i < NND; i += 128) {
            float u = g_usage[b * NND + i];
            if (u < bv) { bv = u; bi = i; }
        }
        asv[tid] = bv; asi[tid] = bi;
        __syncthreads();
        for (int s = 64; s; s >>= 1) {
            if (ht < s) {
                float ov = asv[tid + s]; int oi = asi[tid + s];
                if (ov < asv[tid] || (ov == asv[tid] && oi < asi[tid])) {
                    asv[tid] = ov; asi[tid] = oi;
                }
            }
            __syncthreads();
        }
        if (ht == 0) g_lu[t & 1][b] = asi[tid];
        return;
    }

    const int j0 = jg * 64;
    const float* __restrict__ hn = g_h[sel ^ 1];

    {
        int bb = tid >> 7, idx = tid & 127;
        hs[bb][idx] = ((const float4*)(hn + (size_t)(b0 + bb) * HHD))[idx];
    }
    __syncthreads();

#pragma unroll 2
    for (int jj = 0; jj < 8; ++jj) {
        int j = j0 + wid * 8 + jj;
        const float* wrow = (j < OUTW) ? (Wout + (size_t)j * HHD)
                                       : (Wkey + (size_t)(j - OUTW) * HHD);
        const float4* w4 = (const float4*)wrow;
        float s0 = 0.f, s1 = 0.f;
#pragma unroll
        for (int it = 0; it < 4; ++it) {
            float4 w = w4[lane + 32 * it];
            float4 h0 = hs[0][lane + 32 * it];
            float4 h1 = hs[1][lane + 32 * it];
            s0 += w.x * h0.x + w.y * h0.y + w.z * h0.z + w.w * h0.w;
            s1 += w.x * h1.x + w.y * h1.y + w.z * h1.z + w.w * h1.w;
        }
#pragma unroll
        for (int o = 16; o; o >>= 1) {
            s0 += __shfl_xor_sync(0xffffffffu, s0, o);
            s1 += __shfl_xor_sync(0xffffffffu, s1, o);
        }
        if (lane == 0) { ys[0][wid * 8 + jj] = s0; ys[1][wid * 8 + jj] = s1; }
    }
    __syncthreads();

    if (jg < 2) {
        if (tid < 128) {
            int bb = tid >> 6, jj = tid & 63;
            out[(size_t)t * BB * OUTW + (size_t)(b0 + bb) * OUTW + j0 + jj] =
                ys[bb][jj] + bout[j0 + jj];
        }
    } else if (jg == 6) {
        if (tid < 128) {
            int bb = tid >> 6, jj = tid & 63;
            g_wkey[t & 1][(b0 + bb) * WWD + jj] = ys[bb][jj] + bkey[4 * 64 + jj];
        }
    } else {
        const int kb = (jg - 2) * 64;
        if (tid < 128) {
            int bb = tid >> 6, jj = tid & 63;
            ys[bb][jj] += bkey[kb + jj];
        }
        __syncthreads();
        if (wid < 2) {
            float v0 = ys[wid][lane];
            float v1 = ys[wid][lane + 32];
            float ss = v0 * v0 + v1 * v1;
#pragma unroll
            for (int o = 16; o; o >>= 1) ss += __shfl_xor_sync(0xffffffffu, ss, o);
            if (lane == 0) sinv[wid] = 1.f / (sqrtf(ss) + EPSF);
        }
        __syncthreads();
        if (tid < 128) {
            int bb = tid >> 6, jj = tid & 63;
            g_Kn[(b0 + bb) * (RRD * WWD) + kb + jj] = ys[bb][jj] * sinv[bb];
        }
    }
}

// ===== K3: lazy M-update + sim + stats + chunk partials (one M stream) ======
// grid (16, BB) x 128 threads. Block (nb, b):
//  1. applies the PREVIOUS step's memory write to its 128 M rows while
//     staging them (read-modify-write, riding the stream sim needs anyway),
//  2. computes cosine sims (per-thread rows, zero shuffles),
//  3. emits chunk (max, sumexp) stats,
//  4. emits chunk partials P[r][w] = sum_n exp(sim - m_c) * M[n][w].
__global__ void __launch_bounds__(128) k_simup(const float* __restrict__ alpha,
                                               int t) {
    __shared__ float tA[128 * 33];                   // w 0..31, pitch 33
    __shared__ float tB[128 * 33];                   // w 32..63
    __shared__ __align__(16) float s_kn[RRD * WWD];  // 1 KB
    __shared__ __align__(16) float s_wk[WWD];
    __shared__ float s_ww[128];
    __shared__ float s_sv[4][128];
    __shared__ float s_e[4][128];
    __shared__ float s_mc[4];

    const int b    = blockIdx.y;
    const int nb   = blockIdx.x;
    const int tid  = threadIdx.x;    // 128
    const int wid  = tid >> 5, lane = tid & 31;
    const int n0   = nb * 128;
    const int prev = (t & 1) ^ 1;
    const bool apply = (t > 0);
    const float sa = 1.f / (1.f + expf(-alpha[0]));

    s_kn[tid]       = g_Kn[b * RRD * WWD + tid];
    s_kn[tid + 128] = g_Kn[b * RRD * WWD + tid + 128];
    if (tid < WWD) s_wk[tid] = g_wkey[prev][b * WWD + tid];
    const int lu = g_lu[prev][b];
    {
        // ww for pending update: uses rwsum from step t-2 (buffer t&1)
        float rs = g_rwsum[t & 1][b * NND + n0 + tid];
        s_ww[tid] = sa * rs + ((n0 + tid) == lu ? (1.f - sa) : 0.f);
    }
    __syncthreads();

    float* Mrow = g_M + ((size_t)b * NND + n0) * WWD;

    // stage both halves, applying the pending update in-stream
#pragma unroll
    for (int ph = 0; ph < 2; ++ph) {
        float* tile = ph ? tB : tA;
#pragma unroll
        for (int i = 0; i < 8; ++i) {
            int fid = tid + 128 * i;
            int row = fid >> 3, c4 = fid & 7;
            float4* gp = (float4*)(Mrow + (size_t)row * WWD) + ph * 8 + c4;
            float4 v = *gp;
            if (apply) {
                float ww = s_ww[row];
                const float4 wk4 = *(const float4*)(s_wk + ph * 32 + c4 * 4);
                bool islu = (n0 + row) == lu;
                v.x = (islu ? 0.f : v.x) + ww * wk4.x;
                v.y = (islu ? 0.f : v.y) + ww * wk4.y;
                v.z = (islu ? 0.f : v.z) + ww * wk4.z;
                v.w = (islu ? 0.f : v.w) + ww * wk4.w;
                *gp = v;
            }
            float* dst = tile + row * 33 + c4 * 4;
            dst[0] = v.x; dst[1] = v.y; dst[2] = v.z; dst[3] = v.w;
        }
    }
    __syncthreads();

    // per-thread row reduction (row = tid)
    float ss = 0.f, d0 = 0.f, d1 = 0.f, d2 = 0.f, d3 = 0.f;
#pragma unroll
    for (int ph = 0; ph < 2; ++ph) {
        const float* tr = (ph ? tB : tA) + tid * 33;
        const float4* kk0 = (const float4*)(s_kn + 0 * 64 + ph * 32);
        const float4* kk1 = (const float4*)(s_kn + 1 * 64 + ph * 32);
        const float4* kk2 = (const float4*)(s_kn + 2 * 64 + ph * 32);
        const float4* kk3 = (const float4*)(s_kn + 3 * 64 + ph * 32);
#pragma unroll
        for (int w4 = 0; w4 < 8; ++w4) {
            float m0 = tr[w4 * 4 + 0];
            float m1 = tr[w4 * 4 + 1];
            float m2 = tr[w4 * 4 + 2];
            float m3 = tr[w4 * 4 + 3];
            float4 a = kk0[w4], bb = kk1[w4], c = kk2[w4], d = kk3[w4];
            ss += m0 * m0 + m1 * m1 + m2 * m2 + m3 * m3;
            d0 += m0 * a.x + m1 * a.y + m2 * a.z + m3 * a.w;
            d1 += m0 * bb.x + m1 * bb.y + m2 * bb.z + m3 * bb.w;
            d2 += m0 * c.x + m1 * c.y + m2 * c.z + m3 * c.w;
            d3 += m0 * d.x + m1 * d.y + m2 * d.z + m3 * d.w;
        }
    }

    float inv = 1.f / (sqrtf(ss) + EPSF);
    float s0 = d0 * inv, s1 = d1 * inv, s2 = d2 * inv, s3 = d3 * inv;
    const int n = n0 + tid;
    g_sim[(size_t)(b * RRD + 0) * NND + n] = s0;
    g_sim[(size_t)(b * RRD + 1) * NND + n] = s1;
    g_sim[(size_t)(b * RRD + 2) * NND + n] = s2;
    g_sim[(size_t)(b * RRD + 3) * NND + n] = s3;
    s_sv[0][tid] = s0; s_sv[1][tid] = s1; s_sv[2][tid] = s2; s_sv[3][tid] = s3;
    __syncthreads();

    // warp wid: chunk stats for r = wid
    {
        float v0 = s_sv[wid][lane];
        float v1 = s_sv[wid][lane + 32];
        float v2 = s_sv[wid][lane + 64];
        float v3 = s_sv[wid][lane + 96];
        float m = fmaxf(fmaxf(v0, v1), fmaxf(v2, v3));
#pragma unroll
        for (int o = 16; o; o >>= 1) m = fmaxf(m, __shfl_xor_sync(0xffffffffu, m, o));
        float S = expf(v0 - m) + expf(v1 - m) + expf(v2 - m) + expf(v3 - m);
#pragma unroll
        for (int o = 16; o; o >>= 1) S += __shfl_xor_sync(0xffffffffu, S, o);
        if (lane == 0) {
            g_stats[(b * RRD + wid) * NCHUNK + nb] = make_float2(m, S);
            s_mc[wid] = m;
        }
    }
    __syncthreads();

    // chunk-normalized exps
#pragma unroll
    for (int r = 0; r < 4; ++r)
        s_e[r][tid] = expf(s_sv[r][tid] - s_mc[r]);
    __syncthreads();

    // chunk partials P[r][w] = sum_n e[r][n] * M[n][w]
    {
        const int w  = tid & 63;
        const int rp = tid >> 6;   // 0 or 1; handles r = rp and rp+2
        const float* tcol = ((w < 32) ? tA : tB) + (w & 31);
        float p0 = 0.f, p1 = 0.f;
#pragma unroll 8
        for (int nn = 0; nn < 128; ++nn) {
            float tv = tcol[nn * 33];
            p0 += s_e[rp][nn]     * tv;
            p1 += s_e[rp + 2][nn] * tv;
        }
        g_P[((size_t)(nb * BB + b) * RRD + rp)     * WWD + w] = p0;
        g_P[((size_t)(nb * BB + b) * RRD + rp + 2) * WWD + w] = p1;
    }
}

// ===== K4: finalize — stats combine, rwsum + usage, read_vec (no M pass) ====
// grid (16, BB) x 256 threads. cx==0 block additionally assembles read_vec.
__global__ void __launch_bounds__(256) k_final(const float* __restrict__ alpha,
                                               const float* __restrict__ gamma,
                                               int t) {
    __shared__ float2 s_st[4 * NCHUNK];
    __shared__ float s_m[4], s_is[4];
    __shared__ float srw[4][128];

    const int b   = blockIdx.y;
    const int cx  = blockIdx.x;
    const int tid = threadIdx.x;
    const int cur = t & 1, prev = cur ^ 1;
    const float sa = 1.f / (1.f + expf(-alpha[0]));
    const float gm = gamma[0];
    const int lu = g_lu[cur][b];

    if (tid < 64) s_st[tid] = g_stats[(b * RRD + (tid >> 4)) * NCHUNK + (tid & 15)];
    __syncthreads();
    if (tid < 4) {
        float m = -3.4e38f;
#pragma unroll
        for (int i = 0; i < NCHUNK; ++i) m = fmaxf(m, s_st[tid * NCHUNK + i].x);
        float S = 0.f;
#pragma unroll
        for (int i = 0; i < NCHUNK; ++i) {
            float2 p = s_st[tid * NCHUNK + i];
            S += p.y * expf(p.x - m);
        }
        s_m[tid] = m; s_is[tid] = 1.f / S;
    }
    __syncthreads();

    const int n0 = cx * 128;
#pragma unroll
    for (int k2 = 0; k2 < 2; ++k2) {
        int idx = tid + 256 * k2;
        int r = idx >> 7, nl = idx & 127;
        float sv = g_sim[(size_t)(b * RRD + r) * NND + n0 + nl];
        srw[r][nl] = expf(sv - s_m[r]) * s_is[r];
    }
    __syncthreads();

    if (tid < 128) {
        int nn = n0 + tid;
        float rsum = srw[0][tid] + srw[1][tid] + srw[2][tid] + srw[3][tid];
        g_rwsum[cur][b * NND + nn] = rsum;
        float rprev = g_rwsum[prev][b * NND + nn];
        float wwt = sa * rprev + ((nn == lu) ? (1.f - sa) : 0.f);
        g_usage[b * NND + nn] = gm * g_usage[b * NND + nn] + rsum + wwt;
    }

    // read_vec assembly: only cx==0 block (direct write, no atomics)
    if (cx == 0) {
        const int r = tid >> 6, w = tid & 63;
        float m = s_m[r], is = s_is[r];
        float rv = 0.f;
#pragma unroll
        for (int c = 0; c < NCHUNK; ++c) {
            float2 st = s_st[r * NCHUNK + c];
            rv += expf(st.x - m) * g_P[((size_t)(c * BB + b) * RRD + r) * WWD + w];
        }
        g_read_vec[b * RRD * WWD + tid] = rv * is;
    }
}

// ------------------------------- launcher ------------------------------------
extern "C" void kernel_launch(void* const* d_in, const int* in_sizes, int n_in,
                              void* d_out, int out_size) {
    const float* x_seq = (const float*)d_in[0];
    const float* Wih   = (const float*)d_in[1];
    const float* Whh   = (const float*)d_in[2];
    const float* bih   = (const float*)d_in[3];
    const float* bhh   = (const float*)d_in[4];
    const float* Wout  = (const float*)d_in[5];
    const float* bout  = (const float*)d_in[6];
    const float* Wkey  = (const float*)d_in[7];
    const float* bkey  = (const float*)d_in[8];
    const float* alpha = (const float*)d_in[9];
    const float* gamma = (const float*)d_in[10];
    float* out = (float*)d_out;

    k_reset<<<32768, 256>>>();

    for (int t = 0; t < TT; ++t) {
        const int sel = t & 1;
        k_gates<<<JGATE / 16, 256>>>(x_seq + (size_t)t * BB * INW,
                                     Wih, Whh, bih, bhh, sel);
        k_ok2<<<dim3(8, 32), 256>>>(Wout, Wkey, bout, bkey, out, t, sel);
        k_simup<<<dim3(NCHUNK, BB), 128>>>(alpha, t);
        k_final<<<dim3(16, BB), 256>>>(alpha, gamma, t);
    }
}